// round 12
// baseline (speedup 1.0000x reference)
#include <cuda_runtime.h>
#include <cuda_bf16.h>
#include <cstdint>

#define B_DIM 64
#define H_DIM 512
#define I_DIM 512
#define T_DIM 512

// ---------------------------------------------------------------------------
// Persistent device scratch (static allocation - no runtime allocs)
// ---------------------------------------------------------------------------
__device__ __nv_bfloat16 g_Xt_hi[B_DIM][T_DIM][I_DIM];   // X^T per batch, hi
__device__ __nv_bfloat16 g_Xt_lo[B_DIM][T_DIM][I_DIM];   // X^T per batch, lo
__device__ __nv_bfloat16 g_Wt_hi[H_DIM][I_DIM];          // Wax^T, hi
__device__ __nv_bfloat16 g_Wt_lo[H_DIM][I_DIM];          // Wax^T, lo
__device__ __nv_bfloat16 g_WaaT_hi[H_DIM][H_DIM];        // Waa^T, hi  [h][k]
__device__ __nv_bfloat16 g_WaaT_lo[H_DIM][H_DIM];        // Waa^T, lo
__device__ float         g_bias[H_DIM];                  // bx + ba

// tanh = 1 - 2/(e^{2x}+1) via ex2/rcp approx (~1e-6 rel err, saturates).
__device__ __forceinline__ float ftanh(float x)
{
    float e;
    asm("ex2.approx.f32 %0, %1;" : "=f"(e) : "f"(x * 2.885390081777927f));
    float r;
    asm("rcp.approx.f32 %0, %1;" : "=f"(r) : "f"(e + 1.0f));
    return fmaf(-2.0f, r, 1.0f);
}

__device__ __forceinline__ void mbar_wait(uint32_t mbar, uint32_t parity)
{
    uint32_t done;
    asm volatile(
        "{\n\t.reg .pred p;\n\t"
        "mbarrier.try_wait.parity.acquire.cta.shared::cta.b64 p, [%1], %2;\n\t"
        "selp.b32 %0, 1, 0, p;\n\t}"
        : "=r"(done) : "r"(mbar), "r"(parity) : "memory");
    if (!done) {
        asm volatile(
            "{\n\t.reg .pred P1;\n\t"
            "W_%=:\n\t"
            "mbarrier.try_wait.parity.acquire.cta.shared::cta.b64 P1, [%0], %1, 0x989680;\n\t"
            "@P1 bra.uni D_%=;\n\t"
            "bra.uni W_%=;\n\t"
            "D_%=:\n\t}"
            :: "r"(mbar), "r"(parity) : "memory");
    }
}

// ---------------------------------------------------------------------------
// Convert kernels: transpose + bf16 hi/lo split
// ---------------------------------------------------------------------------
__global__ void __launch_bounds__(256)
convert_x_kernel(const float* __restrict__ X)
{
    __shared__ float tile[32][33];
    const int b  = blockIdx.z;
    const int i0 = blockIdx.x * 32;
    const int t0 = blockIdx.y * 32;
    const int lane = threadIdx.x & 31;
    const int r4   = threadIdx.x >> 5;
    const float* Xb = X + (size_t)b * I_DIM * T_DIM;
#pragma unroll
    for (int rr = 0; rr < 4; rr++) {
        int irow = r4 * 4 + rr;
        tile[irow][lane] = Xb[(size_t)(i0 + irow) * T_DIM + t0 + lane];
    }
    __syncthreads();
#pragma unroll
    for (int rr = 0; rr < 4; rr++) {
        int trow = r4 * 4 + rr;
        float v = tile[lane][trow];
        __nv_bfloat16 hi = __float2bfloat16(v);
        float lo = v - __bfloat162float(hi);
        g_Xt_hi[b][t0 + trow][i0 + lane] = hi;
        g_Xt_lo[b][t0 + trow][i0 + lane] = __float2bfloat16(lo);
    }
}

// [I][H] fp32 -> transposed [H][I] bf16 hi/lo. which: 0 = Wax, 1 = Waa.
// (Destination picked IN DEVICE CODE - device symbols must not be referenced
//  from host code; that was the R11 bug.)
__global__ void __launch_bounds__(256)
convert_w_kernel(const float* __restrict__ W, int which)
{
    __shared__ float tile[32][33];
    const int i0 = blockIdx.x * 32;
    const int h0 = blockIdx.y * 32;
    const int lane = threadIdx.x & 31;
    const int r4   = threadIdx.x >> 5;
    __nv_bfloat16* out_hi = which ? &g_WaaT_hi[0][0] : &g_Wt_hi[0][0];
    __nv_bfloat16* out_lo = which ? &g_WaaT_lo[0][0] : &g_Wt_lo[0][0];
#pragma unroll
    for (int rr = 0; rr < 4; rr++) {
        int irow = r4 * 4 + rr;
        tile[irow][lane] = W[(size_t)(i0 + irow) * H_DIM + h0 + lane];
    }
    __syncthreads();
#pragma unroll
    for (int rr = 0; rr < 4; rr++) {
        int hrow = r4 * 4 + rr;
        float v = tile[lane][hrow];
        __nv_bfloat16 hi = __float2bfloat16(v);
        float lo = v - __bfloat162float(hi);
        out_hi[(size_t)(h0 + hrow) * I_DIM + i0 + lane] = hi;
        out_lo[(size_t)(h0 + hrow) * I_DIM + i0 + lane] = __float2bfloat16(lo);
    }
}

__global__ void __launch_bounds__(512)
bias_kernel(const float* __restrict__ bx, const float* __restrict__ ba)
{
    int h = threadIdx.x;
    g_bias[h] = bx[h] + ba[h];
}

// ---------------------------------------------------------------------------
// mma.sync / ldmatrix helpers
// ---------------------------------------------------------------------------
__device__ __forceinline__ void ldsm4(uint32_t addr, uint32_t* r)
{
    asm volatile("ldmatrix.sync.aligned.m8n8.x4.shared.b16 {%0,%1,%2,%3}, [%4];"
                 : "=r"(r[0]), "=r"(r[1]), "=r"(r[2]), "=r"(r[3]) : "r"(addr));
}
__device__ __forceinline__ void mma16816(float* d, const uint32_t* a,
                                         uint32_t b0, uint32_t b1)
{
    asm volatile(
        "mma.sync.aligned.m16n8k16.row.col.f32.bf16.bf16.f32 "
        "{%0,%1,%2,%3}, {%4,%5,%6,%7}, {%8,%9}, {%0,%1,%2,%3};"
        : "+f"(d[0]), "+f"(d[1]), "+f"(d[2]), "+f"(d[3])
        : "r"(a[0]), "r"(a[1]), "r"(a[2]), "r"(a[3]), "r"(b0), "r"(b1));
}

// ---------------------------------------------------------------------------
// Kernel 1: U = Xt @ Wax^T(+bias), mma.sync bf16 hi/lo (unchanged, proven)
// ---------------------------------------------------------------------------
__global__ void __launch_bounds__(256, 1)
u_gemm_kernel(float* __restrict__ U)
{
    extern __shared__ char smem[];
    const uint32_t smem_u = (uint32_t)__cvta_generic_to_shared(smem);
    const int tid  = threadIdx.x;
    const int wid  = tid >> 5;
    const int lane = tid & 31;
    const int h0 = blockIdx.x * 128;
    const int t0 = blockIdx.y * 128;
    const int b  = blockIdx.z;

    float* bias_s = (float*)(smem + 131072);
    if (tid < 128) bias_s[tid] = g_bias[h0 + tid];

    auto load_stage = [&](int s) {
        const uint32_t buf = smem_u + (uint32_t)(s & 1) * 65536u;
        const int i0 = s * 64;
#pragma unroll
        for (int j = 0; j < 4; j++) {
            int chunk = tid + j * 256;
            int row = chunk >> 3, kc = chunk & 7;
            uint32_t sw = (uint32_t)(row * 128 + kc * 16);
            sw = sw ^ ((sw >> 3) & 0x70);
            const __nv_bfloat16* ga = &g_Xt_hi[b][t0 + row][i0 + kc * 8];
            const __nv_bfloat16* gb = &g_Xt_lo[b][t0 + row][i0 + kc * 8];
            const __nv_bfloat16* gc = &g_Wt_hi[h0 + row][i0 + kc * 8];
            const __nv_bfloat16* gd = &g_Wt_lo[h0 + row][i0 + kc * 8];
            asm volatile("cp.async.cg.shared.global [%0], [%1], 16;"
                         :: "r"(buf + sw), "l"(ga) : "memory");
            asm volatile("cp.async.cg.shared.global [%0], [%1], 16;"
                         :: "r"(buf + 16384u + sw), "l"(gb) : "memory");
            asm volatile("cp.async.cg.shared.global [%0], [%1], 16;"
                         :: "r"(buf + 32768u + sw), "l"(gc) : "memory");
            asm volatile("cp.async.cg.shared.global [%0], [%1], 16;"
                         :: "r"(buf + 49152u + sw), "l"(gd) : "memory");
        }
        asm volatile("cp.async.commit_group;" ::: "memory");
    };

    const int m_off = (wid & 1) * 64;
    const int n_off = (wid >> 1) * 32;

    const uint32_t aRowB = (uint32_t)(m_off + (lane & 15)) * 128u;
    const uint32_t aK8   = (uint32_t)(lane >> 4) * 16u;
    const uint32_t xmA   = (uint32_t)(lane & 7) * 16u;
    const int      brow  = (lane & 7) + ((lane >> 1) & 8);
    const uint32_t bRowB = (uint32_t)(n_off + brow) * 128u;
    const uint32_t bK8   = (uint32_t)(lane & 8) * 2u;
    const uint32_t xmB   = (uint32_t)(lane & 7) * 16u;

    float acc[4][4][4];
#pragma unroll
    for (int i = 0; i < 4; i++)
#pragma unroll
        for (int j = 0; j < 4; j++)
#pragma unroll
            for (int k = 0; k < 4; k++) acc[i][j][k] = 0.0f;

    load_stage(0);
    for (int s = 0; s < 8; s++) {
        if (s < 7) {
            load_stage(s + 1);
            asm volatile("cp.async.wait_group 1;" ::: "memory");
        } else {
            asm volatile("cp.async.wait_group 0;" ::: "memory");
        }
        __syncthreads();

        const uint32_t buf = smem_u + (uint32_t)(s & 1) * 65536u;
#pragma unroll
        for (int k16 = 0; k16 < 4; k16++) {
            const uint32_t colA = ((uint32_t)(k16 * 32) + aK8) ^ xmA;
            const uint32_t colB = ((uint32_t)(k16 * 32) + bK8) ^ xmB;
            uint32_t Ah[4][4], Al[4][4], Bh[2][4], Bl[2][4];
#pragma unroll
            for (int fm = 0; fm < 4; fm++) {
                const uint32_t ad = buf + aRowB + (uint32_t)fm * 2048u + colA;
                ldsm4(ad, Ah[fm]);
                ldsm4(ad + 16384u, Al[fm]);
            }
#pragma unroll
            for (int fn2 = 0; fn2 < 2; fn2++) {
                const uint32_t bd = buf + 32768u + bRowB + (uint32_t)fn2 * 2048u + colB;
                ldsm4(bd, Bh[fn2]);
                ldsm4(bd + 16384u, Bl[fn2]);
            }
#pragma unroll
            for (int fm = 0; fm < 4; fm++) {
#pragma unroll
                for (int fn = 0; fn < 4; fn++) {
                    const int g = fn >> 1, o = (fn & 1) * 2;
                    mma16816(acc[fm][fn], Ah[fm], Bh[g][o], Bh[g][o + 1]);
                    mma16816(acc[fm][fn], Ah[fm], Bl[g][o], Bl[g][o + 1]);
                    mma16816(acc[fm][fn], Al[fm], Bh[g][o], Bh[g][o + 1]);
                }
            }
        }
        __syncthreads();
    }

    const int row_l = lane >> 2;
    const int col_l = (lane & 3) * 2;
#pragma unroll
    for (int fm = 0; fm < 4; fm++) {
#pragma unroll
        for (int fn = 0; fn < 4; fn++) {
            const int cl = n_off + fn * 8 + col_l;
            const float bi0 = bias_s[cl], bi1 = bias_s[cl + 1];
            const int r0 = t0 + m_off + fm * 16 + row_l;
            float* up0 = U + (size_t)r0 * (B_DIM * H_DIM) + (size_t)b * H_DIM + h0 + cl;
            float2 v0 = make_float2(acc[fm][fn][0] + bi0, acc[fm][fn][1] + bi1);
            *(float2*)up0 = v0;
            float* up1 = up0 + 8 * (B_DIM * H_DIM);
            float2 v1 = make_float2(acc[fm][fn][2] + bi0, acc[fm][fn][3] + bi1);
            *(float2*)up1 = v1;
        }
    }
}

// ---------------------------------------------------------------------------
// Kernel 2: cluster recurrence, HMMA edition.
// D[64h x 8n] = Waa^T(64x512) @ a(512x8, 4 pad) per CTA/step, m16n8k16 bf16
// hi/lo (3 passes). Waa^T frags preloaded to REGISTERS once (static operand).
// a transported as packed (bf16hi|bf16lo<<16) u32 words in a [k][b] grid;
// B-frags built with 4 LDS + 4 PRMT per k16. 8 warps = 8 k-strips;
// per-(src,parity) mbarriers + st.async.b32 fanout (R9-proven protocol).
// ---------------------------------------------------------------------------
__global__ void __launch_bounds__(256, 1) __cluster_dims__(8, 1, 1)
recurrence_kernel(float* __restrict__ A)
{
    extern __shared__ float sm[];
    // sm[0..31]: 16 mbarriers: bar[src][parity] at byte src*16 + par*8
    uint32_t* ab = (uint32_t*)(sm + 32);   // [3 buf][512 k][4 b] u32 = 6144
    float* Red   = sm + 32 + 6144;         // [2 par][8 ks][4 b][64 hh] = 4096
    char* smc = (char*)sm;                 // W tiles at byte 41088: hi,lo 64KB

    const int tid  = threadIdx.x;
    const int wid  = tid >> 5;             // warp = k-strip 0..7
    const int lane = tid & 31;
    uint32_t rank;
    asm("mov.u32 %0, %%cluster_ctarank;" : "=r"(rank));
    const int cl = blockIdx.x >> 3;
    const int b0 = cl * 4;
    const int n0 = (int)rank * 64;

    const uint32_t mbar0 = (uint32_t)__cvta_generic_to_shared(sm);
    const uint32_t ab_s  = (uint32_t)__cvta_generic_to_shared(ab);
    const uint32_t wh_s  = mbar0 + 41088u;

    uint32_t peer_ab[8];
#pragma unroll
    for (int r = 0; r < 8; r++) {
        asm("mapa.shared::cluster.u32 %0, %1, %2;"
            : "=r"(peer_ab[r]) : "r"(ab_s), "r"(r));
    }

    // Stage W^T slice (rows h = n0..n0+63, full k) swizzled for ldmatrix.
    for (int i = tid; i < 4096; i += 256) {
        int h = i >> 6, u16i = i & 63;
        uint32_t dst = 41088u + (uint32_t)h * 1024u +
                       (((uint32_t)u16i * 16u) ^ ((uint32_t)(h & 7) << 4));
        *(uint4*)(smc + dst) = *(const uint4*)&g_WaaT_hi[n0 + h][u16i * 8];
        *(uint4*)(smc + dst + 65536u) = *(const uint4*)&g_WaaT_lo[n0 + h][u16i * 8];
    }

    if (tid < 16) {
        asm volatile("mbarrier.init.shared.b64 [%0], 1;"
                     :: "r"(mbar0 + tid * 8) : "memory");
    }
    for (int i = tid; i < 2048; i += 256) ab[i] = 0u;   // a_0 = 0 (buf 0)
    __syncthreads();
    if (tid < 16) {                                      // arm both parities
        asm volatile("mbarrier.arrive.expect_tx.shared.b64 _, [%0], %1;"
                     :: "r"(mbar0 + tid * 8), "r"(1024u) : "memory");
    }

    // Preload this warp's static A-operand (Waa^T) fragments into registers:
    // Afrag[kc][mt][hi/lo interleaved]: 4 kc x 4 mt x (4 hi + 4 lo) = 128 regs.
    const int aRow  = lane & 15;
    const int aHalf = lane >> 4;
    uint32_t Afh[4][4][4], Afl[4][4][4];
#pragma unroll
    for (int kc = 0; kc < 4; kc++) {
        const uint32_t kcol = ((uint32_t)(wid * 128 + kc * 32 + aHalf * 16))
                              ^ ((uint32_t)(aRow & 7) << 4);
#pragma unroll
        for (int mt = 0; mt < 4; mt++) {
            const uint32_t ad = wh_s + (uint32_t)(mt * 16 + aRow) * 1024u + kcol;
            ldsm4(ad, Afh[kc][mt]);
            ldsm4(ad + 65536u, Afl[kc][mt]);
        }
    }

    asm volatile("barrier.cluster.arrive.aligned;" ::: "memory");
    asm volatile("barrier.cluster.wait.aligned;" ::: "memory");

    const int eb = tid >> 6;              // epilogue batch 0..3
    const int eh = tid & 63;              // epilogue hidden-within-slice
    const size_t ebase = (size_t)(b0 + eb) * H_DIM + n0 + eh;
    const uint32_t eoff = rank * 1024u + (uint32_t)(eh * 4 + eb) * 4u;

    const bool bAct = (lane < 16);
    const int  bK   = (lane & 3) * 2;
    const int  bB   = lane >> 2;          // 0..3 real for lanes<16

    for (int t = 0; t < T_DIM; t++) {
        const int cb = t % 3, nb2 = (t + 1) % 3;

        float u = __ldcs(&A[(size_t)t * (B_DIM * H_DIM) + ebase]);

        if (t > 0) {
            const uint32_t obj = mbar0 + (uint32_t)(wid * 16 + ((t - 1) & 1) * 8);
            mbar_wait(obj, (uint32_t)(((t - 1) >> 1) & 1));
            if (lane == 0) {
                asm volatile("mbarrier.arrive.expect_tx.shared.b64 _, [%0], %1;"
                             :: "r"(obj), "r"(1024u) : "memory");
            }
        }

        float D[4][4];
#pragma unroll
        for (int mt = 0; mt < 4; mt++)
#pragma unroll
            for (int j = 0; j < 4; j++) D[mt][j] = 0.0f;

        const uint32_t aboff = 128u + (uint32_t)cb * 8192u;   // ab byte offset
#pragma unroll
        for (int kc = 0; kc < 4; kc++) {
            const int kb = wid * 64 + kc * 16;
            uint32_t b0h = 0, b0l = 0, b1h = 0, b1l = 0;
            if (bAct) {
                uint32_t w0 = *(uint32_t*)(smc + aboff + ((kb + bK) * 4 + bB) * 4);
                uint32_t w1 = *(uint32_t*)(smc + aboff + ((kb + bK + 1) * 4 + bB) * 4);
                uint32_t w2 = *(uint32_t*)(smc + aboff + ((kb + bK + 8) * 4 + bB) * 4);
                uint32_t w3 = *(uint32_t*)(smc + aboff + ((kb + bK + 9) * 4 + bB) * 4);
                b0h = __byte_perm(w0, w1, 0x5410);
                b0l = __byte_perm(w0, w1, 0x7632);
                b1h = __byte_perm(w2, w3, 0x5410);
                b1l = __byte_perm(w2, w3, 0x7632);
            }
#pragma unroll
            for (int mt = 0; mt < 4; mt++) {
                mma16816(D[mt], Afh[kc][mt], b0h, b1h);
                mma16816(D[mt], Afh[kc][mt], b0l, b1l);
                mma16816(D[mt], Afl[kc][mt], b0h, b1h);
            }
        }

        // Scatter D partials: Red[t&1][wid][b][h]
        if ((lane & 3) < 2) {
            float* Rp = Red + (t & 1) * 2048 + wid * 256;
            const int bcol = (lane & 3) * 2;
            const int hr = lane >> 2;
#pragma unroll
            for (int mt = 0; mt < 4; mt++) {
                const int h = mt * 16 + hr;
                Rp[bcol * 64 + h]           = D[mt][0];
                Rp[(bcol + 1) * 64 + h]     = D[mt][1];
                Rp[bcol * 64 + h + 8]       = D[mt][2];
                Rp[(bcol + 1) * 64 + h + 8] = D[mt][3];
            }
        }
        __syncthreads();

        // Epilogue: reduce 8 strip partials + U, tanh, fanout, store.
        {
            const float* Rr = Red + (t & 1) * 2048 + eb * 64 + eh;
            float s = u;
#pragma unroll
            for (int w8 = 0; w8 < 8; w8++)
                s += Rr[w8 * 256];
            float val = ftanh(s);

            if (t < T_DIM - 1) {
                __nv_bfloat16 bh = __float2bfloat16(val);
                float rem = val - __bfloat162float(bh);
                __nv_bfloat16 bl = __float2bfloat16(rem);
                uint32_t word = (uint32_t)__bfloat16_as_ushort(bh)
                              | ((uint32_t)__bfloat16_as_ushort(bl) << 16);
                const uint32_t doff = (uint32_t)nb2 * 8192u + eoff;
                const uint32_t boff = rank * 16u + (uint32_t)(t & 1) * 8u;
#pragma unroll
                for (int r = 0; r < 8; r++) {
                    const uint32_t da = peer_ab[r] + doff;
                    const uint32_t ma = peer_ab[r] - 128u + boff;
                    asm volatile(
                        "st.async.shared::cluster.mbarrier::complete_tx::bytes.b32 "
                        "[%0], %1, [%2];"
                        :: "r"(da), "r"(word), "r"(ma) : "memory");
                }
            }
            __stcs(&A[(size_t)t * (B_DIM * H_DIM) + ebase], val);
        }
    }

    asm volatile("barrier.cluster.arrive.aligned;" ::: "memory");
    asm volatile("barrier.cluster.wait.aligned;" ::: "memory");
}

// ---------------------------------------------------------------------------
extern "C" void kernel_launch(void* const* d_in, const int* in_sizes, int n_in,
                              void* d_out, int out_size)
{
    const float* X   = (const float*)d_in[0];
    const float* Wax = (const float*)d_in[1];
    const float* Waa = (const float*)d_in[2];
    const float* bx  = (const float*)d_in[3];
    const float* ba  = (const float*)d_in[4];
    float* out = (float*)d_out;

    const int gemm_smem = 132 * 1024;
    cudaFuncSetAttribute(u_gemm_kernel,
                         cudaFuncAttributeMaxDynamicSharedMemorySize, gemm_smem);
    const int rec_smem = 41088 + 2 * 65536;   // 172160 B (pins 1 CTA/SM)
    cudaFuncSetAttribute(recurrence_kernel,
                         cudaFuncAttributeMaxDynamicSharedMemorySize, rec_smem);

    convert_x_kernel<<<dim3(16, 16, 64), 256>>>(X);
    convert_w_kernel<<<dim3(16, 16), 256>>>(Wax, 0);
    convert_w_kernel<<<dim3(16, 16), 256>>>(Waa, 1);
    bias_kernel<<<1, 512>>>(bx, ba);
    u_gemm_kernel<<<dim3(4, 4, 64), 256, gemm_smem>>>(out);
    recurrence_kernel<<<128, 256, rec_smem>>>(out);
}

// round 13
// speedup vs baseline: 1.1223x; 1.1223x over previous
#include <cuda_runtime.h>
#include <cuda_bf16.h>
#include <cstdint>

#define B_DIM 64
#define H_DIM 512
#define I_DIM 512
#define T_DIM 512

// ---------------------------------------------------------------------------
// Persistent device scratch (static allocation - no runtime allocs)
// ---------------------------------------------------------------------------
__device__ __nv_bfloat16 g_Xt_hi[B_DIM][T_DIM][I_DIM];   // X^T per batch, hi
__device__ __nv_bfloat16 g_Xt_lo[B_DIM][T_DIM][I_DIM];   // X^T per batch, lo
__device__ __nv_bfloat16 g_Wt_hi[H_DIM][I_DIM];          // Wax^T, hi
__device__ __nv_bfloat16 g_Wt_lo[H_DIM][I_DIM];          // Wax^T, lo
__device__ __nv_bfloat16 g_WaaT_hi[H_DIM][H_DIM];        // Waa^T, hi  [h][k]
__device__ __nv_bfloat16 g_WaaT_lo[H_DIM][H_DIM];        // Waa^T, lo

// tanh = 1 - 2/(e^{2x}+1) via ex2/rcp approx (~1e-6 rel err, saturates).
__device__ __forceinline__ float ftanh(float x)
{
    float e;
    asm("ex2.approx.f32 %0, %1;" : "=f"(e) : "f"(x * 2.885390081777927f));
    float r;
    asm("rcp.approx.f32 %0, %1;" : "=f"(r) : "f"(e + 1.0f));
    return fmaf(-2.0f, r, 1.0f);
}

__device__ __forceinline__ void mbar_wait(uint32_t mbar, uint32_t parity)
{
    uint32_t done;
    asm volatile(
        "{\n\t.reg .pred p;\n\t"
        "mbarrier.try_wait.parity.acquire.cta.shared::cta.b64 p, [%1], %2;\n\t"
        "selp.b32 %0, 1, 0, p;\n\t}"
        : "=r"(done) : "r"(mbar), "r"(parity) : "memory");
    if (!done) {
        asm volatile(
            "{\n\t.reg .pred P1;\n\t"
            "W_%=:\n\t"
            "mbarrier.try_wait.parity.acquire.cta.shared::cta.b64 P1, [%0], %1, 0x989680;\n\t"
            "@P1 bra.uni D_%=;\n\t"
            "bra.uni W_%=;\n\t"
            "D_%=:\n\t}"
            :: "r"(mbar), "r"(parity) : "memory");
    }
}

// ---------------------------------------------------------------------------
// Convert kernels: transpose + bf16 hi/lo split
// ---------------------------------------------------------------------------
__global__ void __launch_bounds__(256)
convert_x_kernel(const float* __restrict__ X)
{
    __shared__ float tile[32][33];
    const int b  = blockIdx.z;
    const int i0 = blockIdx.x * 32;
    const int t0 = blockIdx.y * 32;
    const int lane = threadIdx.x & 31;
    const int r4   = threadIdx.x >> 5;
    const float* Xb = X + (size_t)b * I_DIM * T_DIM;
#pragma unroll
    for (int rr = 0; rr < 4; rr++) {
        int irow = r4 * 4 + rr;
        tile[irow][lane] = Xb[(size_t)(i0 + irow) * T_DIM + t0 + lane];
    }
    __syncthreads();
#pragma unroll
    for (int rr = 0; rr < 4; rr++) {
        int trow = r4 * 4 + rr;
        float v = tile[lane][trow];
        __nv_bfloat16 hi = __float2bfloat16(v);
        float lo = v - __bfloat162float(hi);
        g_Xt_hi[b][t0 + trow][i0 + lane] = hi;
        g_Xt_lo[b][t0 + trow][i0 + lane] = __float2bfloat16(lo);
    }
}

// [I][H] fp32 -> transposed [H][I] bf16 hi/lo. which: 0 = Wax, 1 = Waa.
// (Destination picked IN DEVICE CODE - device symbols, host shadow is invalid.)
__global__ void __launch_bounds__(256)
convert_w_kernel(const float* __restrict__ W, int which)
{
    __shared__ float tile[32][33];
    const int i0 = blockIdx.x * 32;
    const int h0 = blockIdx.y * 32;
    const int lane = threadIdx.x & 31;
    const int r4   = threadIdx.x >> 5;
    __nv_bfloat16* out_hi = which ? &g_WaaT_hi[0][0] : &g_Wt_hi[0][0];
    __nv_bfloat16* out_lo = which ? &g_WaaT_lo[0][0] : &g_Wt_lo[0][0];
#pragma unroll
    for (int rr = 0; rr < 4; rr++) {
        int irow = r4 * 4 + rr;
        tile[irow][lane] = W[(size_t)(i0 + irow) * H_DIM + h0 + lane];
    }
    __syncthreads();
#pragma unroll
    for (int rr = 0; rr < 4; rr++) {
        int hrow = r4 * 4 + rr;
        float v = tile[lane][hrow];
        __nv_bfloat16 hi = __float2bfloat16(v);
        float lo = v - __bfloat162float(hi);
        out_hi[(size_t)(h0 + hrow) * I_DIM + i0 + lane] = hi;
        out_lo[(size_t)(h0 + hrow) * I_DIM + i0 + lane] = __float2bfloat16(lo);
    }
}

// ---------------------------------------------------------------------------
// mma.sync / ldmatrix helpers
// ---------------------------------------------------------------------------
__device__ __forceinline__ void ldsm4(uint32_t addr, uint32_t* r)
{
    asm volatile("ldmatrix.sync.aligned.m8n8.x4.shared.b16 {%0,%1,%2,%3}, [%4];"
                 : "=r"(r[0]), "=r"(r[1]), "=r"(r[2]), "=r"(r[3]) : "r"(addr));
}
__device__ __forceinline__ void mma16816(float* d, const uint32_t* a,
                                         uint32_t b0, uint32_t b1)
{
    asm volatile(
        "mma.sync.aligned.m16n8k16.row.col.f32.bf16.bf16.f32 "
        "{%0,%1,%2,%3}, {%4,%5,%6,%7}, {%8,%9}, {%0,%1,%2,%3};"
        : "+f"(d[0]), "+f"(d[1]), "+f"(d[2]), "+f"(d[3])
        : "r"(a[0]), "r"(a[1]), "r"(a[2]), "r"(a[3]), "r"(b0), "r"(b1));
}

// ---------------------------------------------------------------------------
// Kernel 1: U = Xt @ Wax^T(+bias), mma.sync bf16 hi/lo (proven; bias fused)
// ---------------------------------------------------------------------------
__global__ void __launch_bounds__(256, 1)
u_gemm_kernel(float* __restrict__ U,
              const float* __restrict__ bx, const float* __restrict__ ba)
{
    extern __shared__ char smem[];
    const uint32_t smem_u = (uint32_t)__cvta_generic_to_shared(smem);
    const int tid  = threadIdx.x;
    const int wid  = tid >> 5;
    const int lane = tid & 31;
    const int h0 = blockIdx.x * 128;
    const int t0 = blockIdx.y * 128;
    const int b  = blockIdx.z;

    float* bias_s = (float*)(smem + 131072);
    if (tid < 128) bias_s[tid] = bx[h0 + tid] + ba[h0 + tid];

    auto load_stage = [&](int s) {
        const uint32_t buf = smem_u + (uint32_t)(s & 1) * 65536u;
        const int i0 = s * 64;
#pragma unroll
        for (int j = 0; j < 4; j++) {
            int chunk = tid + j * 256;
            int row = chunk >> 3, kc = chunk & 7;
            uint32_t sw = (uint32_t)(row * 128 + kc * 16);
            sw = sw ^ ((sw >> 3) & 0x70);
            const __nv_bfloat16* ga = &g_Xt_hi[b][t0 + row][i0 + kc * 8];
            const __nv_bfloat16* gb = &g_Xt_lo[b][t0 + row][i0 + kc * 8];
            const __nv_bfloat16* gc = &g_Wt_hi[h0 + row][i0 + kc * 8];
            const __nv_bfloat16* gd = &g_Wt_lo[h0 + row][i0 + kc * 8];
            asm volatile("cp.async.cg.shared.global [%0], [%1], 16;"
                         :: "r"(buf + sw), "l"(ga) : "memory");
            asm volatile("cp.async.cg.shared.global [%0], [%1], 16;"
                         :: "r"(buf + 16384u + sw), "l"(gb) : "memory");
            asm volatile("cp.async.cg.shared.global [%0], [%1], 16;"
                         :: "r"(buf + 32768u + sw), "l"(gc) : "memory");
            asm volatile("cp.async.cg.shared.global [%0], [%1], 16;"
                         :: "r"(buf + 49152u + sw), "l"(gd) : "memory");
        }
        asm volatile("cp.async.commit_group;" ::: "memory");
    };

    const int m_off = (wid & 1) * 64;
    const int n_off = (wid >> 1) * 32;

    const uint32_t aRowB = (uint32_t)(m_off + (lane & 15)) * 128u;
    const uint32_t aK8   = (uint32_t)(lane >> 4) * 16u;
    const uint32_t xmA   = (uint32_t)(lane & 7) * 16u;
    const int      brow  = (lane & 7) + ((lane >> 1) & 8);
    const uint32_t bRowB = (uint32_t)(n_off + brow) * 128u;
    const uint32_t bK8   = (uint32_t)(lane & 8) * 2u;
    const uint32_t xmB   = (uint32_t)(lane & 7) * 16u;

    float acc[4][4][4];
#pragma unroll
    for (int i = 0; i < 4; i++)
#pragma unroll
        for (int j = 0; j < 4; j++)
#pragma unroll
            for (int k = 0; k < 4; k++) acc[i][j][k] = 0.0f;

    load_stage(0);
    for (int s = 0; s < 8; s++) {
        if (s < 7) {
            load_stage(s + 1);
            asm volatile("cp.async.wait_group 1;" ::: "memory");
        } else {
            asm volatile("cp.async.wait_group 0;" ::: "memory");
        }
        __syncthreads();

        const uint32_t buf = smem_u + (uint32_t)(s & 1) * 65536u;
#pragma unroll
        for (int k16 = 0; k16 < 4; k16++) {
            const uint32_t colA = ((uint32_t)(k16 * 32) + aK8) ^ xmA;
            const uint32_t colB = ((uint32_t)(k16 * 32) + bK8) ^ xmB;
            uint32_t Ah[4][4], Al[4][4], Bh[2][4], Bl[2][4];
#pragma unroll
            for (int fm = 0; fm < 4; fm++) {
                const uint32_t ad = buf + aRowB + (uint32_t)fm * 2048u + colA;
                ldsm4(ad, Ah[fm]);
                ldsm4(ad + 16384u, Al[fm]);
            }
#pragma unroll
            for (int fn2 = 0; fn2 < 2; fn2++) {
                const uint32_t bd = buf + 32768u + bRowB + (uint32_t)fn2 * 2048u + colB;
                ldsm4(bd, Bh[fn2]);
                ldsm4(bd + 16384u, Bl[fn2]);
            }
#pragma unroll
            for (int fm = 0; fm < 4; fm++) {
#pragma unroll
                for (int fn = 0; fn < 4; fn++) {
                    const int g = fn >> 1, o = (fn & 1) * 2;
                    mma16816(acc[fm][fn], Ah[fm], Bh[g][o], Bh[g][o + 1]);
                    mma16816(acc[fm][fn], Ah[fm], Bl[g][o], Bl[g][o + 1]);
                    mma16816(acc[fm][fn], Al[fm], Bh[g][o], Bh[g][o + 1]);
                }
            }
        }
        __syncthreads();
    }

    const int row_l = lane >> 2;
    const int col_l = (lane & 3) * 2;
#pragma unroll
    for (int fm = 0; fm < 4; fm++) {
#pragma unroll
        for (int fn = 0; fn < 4; fn++) {
            const int cl = n_off + fn * 8 + col_l;
            const float bi0 = bias_s[cl], bi1 = bias_s[cl + 1];
            const int r0 = t0 + m_off + fm * 16 + row_l;
            float* up0 = U + (size_t)r0 * (B_DIM * H_DIM) + (size_t)b * H_DIM + h0 + cl;
            float2 v0 = make_float2(acc[fm][fn][0] + bi0, acc[fm][fn][1] + bi1);
            *(float2*)up0 = v0;
            float* up1 = up0 + 8 * (B_DIM * H_DIM);
            float2 v1 = make_float2(acc[fm][fn][2] + bi0, acc[fm][fn][3] + bi1);
            *(float2*)up1 = v1;
        }
    }
}

// ---------------------------------------------------------------------------
// Kernel 2: cluster recurrence, HMMA edition v2 (fix R12 perf).
// 512 threads / 16 warps; warp w owns k-strip [32w, 32w+32).
// Hi A-frags (Waa^T) in registers (32 regs); lo A-frags ldmatrix'd in-loop.
// Two warps share each per-(src,parity) barrier; st.async bf16-pair fanout.
// SMEM bytes: [0,128) mbarriers | [128,24704) ab[3][512][4]u32 |
//             [24704,57472) Red[2][16][4][64] | [57472,+128KB) Whi,Wlo.
// ---------------------------------------------------------------------------
#define REC_WBASE 57472u
#define REC_SMEM  (57472 + 2 * 65536)

__global__ void __launch_bounds__(512, 1) __cluster_dims__(8, 1, 1)
recurrence_kernel(float* __restrict__ A)
{
    extern __shared__ float sm[];
    uint32_t* ab = (uint32_t*)(sm + 32);
    float* Red   = sm + 32 + 6144;
    char* smc    = (char*)sm;

    const int tid  = threadIdx.x;
    const int wid  = tid >> 5;             // warp = k-strip 0..15
    const int lane = tid & 31;
    uint32_t rank;
    asm("mov.u32 %0, %%cluster_ctarank;" : "=r"(rank));
    const int cl = blockIdx.x >> 3;
    const int b0 = cl * 4;
    const int n0 = (int)rank * 64;

    const uint32_t mbar0 = (uint32_t)__cvta_generic_to_shared(sm);
    const uint32_t ab_s  = (uint32_t)__cvta_generic_to_shared(ab);
    const uint32_t wh_s  = mbar0 + REC_WBASE;

    uint32_t peer_ab[8];
#pragma unroll
    for (int r = 0; r < 8; r++) {
        asm("mapa.shared::cluster.u32 %0, %1, %2;"
            : "=r"(peer_ab[r]) : "r"(ab_s), "r"(r));
    }

    // Stage W^T slice (rows h = n0..n0+63, full k=512) swizzled for ldmatrix.
    for (int i = tid; i < 4096; i += 512) {
        int h = i >> 6, u16i = i & 63;
        uint32_t dst = REC_WBASE + (uint32_t)h * 1024u +
                       (((uint32_t)u16i * 16u) ^ ((uint32_t)(h & 7) << 4));
        *(uint4*)(smc + dst) = *(const uint4*)&g_WaaT_hi[n0 + h][u16i * 8];
        *(uint4*)(smc + dst + 65536u) = *(const uint4*)&g_WaaT_lo[n0 + h][u16i * 8];
    }

    if (tid < 16) {
        asm volatile("mbarrier.init.shared.b64 [%0], 1;"
                     :: "r"(mbar0 + tid * 8) : "memory");
    }
    for (int i = tid; i < 2048; i += 512) ab[i] = 0u;   // a_0 = 0 (buf 0)
    __syncthreads();
    if (tid < 16) {                                      // arm both parities
        asm volatile("mbarrier.arrive.expect_tx.shared.b64 _, [%0], %1;"
                     :: "r"(mbar0 + tid * 8), "r"(1024u) : "memory");
    }

    // Preload hi A-frags: 2 kc x 4 mt x 4 = 32 regs; keep lo addresses cheap.
    const int aRow  = lane & 15;
    const int aHalf = lane >> 4;
    const uint32_t rowB  = wh_s + (uint32_t)aRow * 1024u;
    const uint32_t kcol0 = ((uint32_t)(wid * 64 + aHalf * 16))
                           ^ ((uint32_t)(aRow & 7) << 4);
    const uint32_t kcol1 = ((uint32_t)(wid * 64 + 32 + aHalf * 16))
                           ^ ((uint32_t)(aRow & 7) << 4);
    uint32_t Afh[2][4][4];
#pragma unroll
    for (int mt = 0; mt < 4; mt++) {
        ldsm4(rowB + (uint32_t)mt * 16384u + kcol0, Afh[0][mt]);
        ldsm4(rowB + (uint32_t)mt * 16384u + kcol1, Afh[1][mt]);
    }

    asm volatile("barrier.cluster.arrive.aligned;" ::: "memory");
    asm volatile("barrier.cluster.wait.aligned;" ::: "memory");

    const int eb = (tid >> 6) & 3;        // epilogue batch (tid<256)
    const int eh = tid & 63;
    const size_t ebase = (size_t)(b0 + eb) * H_DIM + n0 + eh;
    const uint32_t eoff = rank * 1024u + (uint32_t)(eh * 4 + eb) * 4u;

    const bool bAct = (lane < 16);
    const int  bK   = (lane & 3) * 2;
    const int  bB   = lane >> 2;          // real batch col for lanes<16
    const int  src  = wid >> 1;           // source rank for this strip

    for (int t = 0; t < T_DIM; t++) {
        const int cb = t % 3, nb2 = (t + 1) % 3;

        float u = 0.0f;
        if (tid < 256) u = __ldcs(&A[(size_t)t * (B_DIM * H_DIM) + ebase]);

        if (t > 0) {
            const uint32_t obj = mbar0 + (uint32_t)(src * 16 + ((t - 1) & 1) * 8);
            mbar_wait(obj, (uint32_t)(((t - 1) >> 1) & 1));
            if ((wid & 1) == 0 && lane == 0) {   // single re-armer per object
                asm volatile("mbarrier.arrive.expect_tx.shared.b64 _, [%0], %1;"
                             :: "r"(obj), "r"(1024u) : "memory");
            }
        }

        float D[4][4];
#pragma unroll
        for (int mt = 0; mt < 4; mt++)
#pragma unroll
            for (int j = 0; j < 4; j++) D[mt][j] = 0.0f;

        const uint32_t aboff = 128u + (uint32_t)cb * 8192u;
#pragma unroll
        for (int kc = 0; kc < 2; kc++) {
            const int kb = wid * 32 + kc * 16;
            uint32_t b0h = 0, b0l = 0, b1h = 0, b1l = 0;
            if (bAct) {
                uint32_t w0 = *(uint32_t*)(smc + aboff + ((kb + bK) * 4 + bB) * 4);
                uint32_t w1 = *(uint32_t*)(smc + aboff + ((kb + bK + 1) * 4 + bB) * 4);
                uint32_t w2 = *(uint32_t*)(smc + aboff + ((kb + bK + 8) * 4 + bB) * 4);
                uint32_t w3 = *(uint32_t*)(smc + aboff + ((kb + bK + 9) * 4 + bB) * 4);
                b0h = __byte_perm(w0, w1, 0x5410);
                b0l = __byte_perm(w0, w1, 0x7632);
                b1h = __byte_perm(w2, w3, 0x5410);
                b1l = __byte_perm(w2, w3, 0x7632);
            }
            const uint32_t kcol = kc ? kcol1 : kcol0;
#pragma unroll
            for (int mt = 0; mt < 4; mt++) {
                uint32_t Afl[4];
                ldsm4(rowB + (uint32_t)mt * 16384u + kcol + 65536u, Afl);
                mma16816(D[mt], Afh[kc][mt], b0h, b1h);
                mma16816(D[mt], Afh[kc][mt], b0l, b1l);
                mma16816(D[mt], Afl, b0h, b1h);
            }
        }

        // Scatter D partials: Red[t&1][wid][b][h]
        if ((lane & 3) < 2) {
            float* Rp = Red + (t & 1) * 4096 + wid * 256;
            const int bcol = (lane & 3) * 2;
            const int hr = lane >> 2;
#pragma unroll
            for (int mt = 0; mt < 4; mt++) {
                const int h = mt * 16 + hr;
                Rp[bcol * 64 + h]           = D[mt][0];
                Rp[(bcol + 1) * 64 + h]     = D[mt][1];
                Rp[bcol * 64 + h + 8]       = D[mt][2];
                Rp[(bcol + 1) * 64 + h + 8] = D[mt][3];
            }
        }
        __syncthreads();

        if (tid < 256) {
            const float* Rr = Red + (t & 1) * 4096 + eb * 64 + eh;
            float s = u;
#pragma unroll
            for (int w16 = 0; w16 < 16; w16++)
                s += Rr[w16 * 256];
            float val = ftanh(s);

            if (t < T_DIM - 1) {
                __nv_bfloat16 bh = __float2bfloat16(val);
                float rem = val - __bfloat162float(bh);
                __nv_bfloat16 bl = __float2bfloat16(rem);
                uint32_t word = (uint32_t)__bfloat16_as_ushort(bh)
                              | ((uint32_t)__bfloat16_as_ushort(bl) << 16);
                const uint32_t doff = (uint32_t)nb2 * 8192u + eoff;
                const uint32_t boff = rank * 16u + (uint32_t)(t & 1) * 8u;
#pragma unroll
                for (int r = 0; r < 8; r++) {
                    const uint32_t da = peer_ab[r] + doff;
                    const uint32_t ma = peer_ab[r] - 128u + boff;
                    asm volatile(
                        "st.async.shared::cluster.mbarrier::complete_tx::bytes.b32 "
                        "[%0], %1, [%2];"
                        :: "r"(da), "r"(word), "r"(ma) : "memory");
                }
            }
            __stcs(&A[(size_t)t * (B_DIM * H_DIM) + ebase], val);
        }
    }

    asm volatile("barrier.cluster.arrive.aligned;" ::: "memory");
    asm volatile("barrier.cluster.wait.aligned;" ::: "memory");
}

// ---------------------------------------------------------------------------
extern "C" void kernel_launch(void* const* d_in, const int* in_sizes, int n_in,
                              void* d_out, int out_size)
{
    const float* X   = (const float*)d_in[0];
    const float* Wax = (const float*)d_in[1];
    const float* Waa = (const float*)d_in[2];
    const float* bx  = (const float*)d_in[3];
    const float* ba  = (const float*)d_in[4];
    float* out = (float*)d_out;

    const int gemm_smem = 132 * 1024;
    cudaFuncSetAttribute(u_gemm_kernel,
                         cudaFuncAttributeMaxDynamicSharedMemorySize, gemm_smem);
    cudaFuncSetAttribute(recurrence_kernel,
                         cudaFuncAttributeMaxDynamicSharedMemorySize, REC_SMEM);

    convert_x_kernel<<<dim3(16, 16, 64), 256>>>(X);
    convert_w_kernel<<<dim3(16, 16), 256>>>(Wax, 0);
    convert_w_kernel<<<dim3(16, 16), 256>>>(Waa, 1);
    u_gemm_kernel<<<dim3(4, 4, 64), 256, gemm_smem>>>(out, bx, ba);
    recurrence_kernel<<<128, 512, REC_SMEM>>>(out);
}

// round 15
// speedup vs baseline: 1.6293x; 1.4517x over previous
#include <cuda_runtime.h>
#include <cuda_bf16.h>
#include <cstdint>

#define B_DIM 64
#define H_DIM 512
#define I_DIM 512
#define T_DIM 512

// ---------------------------------------------------------------------------
// Persistent device scratch (static allocation - no runtime allocs)
// ---------------------------------------------------------------------------
__device__ __nv_bfloat16 g_Xt_hi[B_DIM][T_DIM][I_DIM];   // X^T per batch, hi
__device__ __nv_bfloat16 g_Xt_lo[B_DIM][T_DIM][I_DIM];   // X^T per batch, lo
__device__ __nv_bfloat16 g_Wt_hi[H_DIM][I_DIM];          // Wax^T, hi
__device__ __nv_bfloat16 g_Wt_lo[H_DIM][I_DIM];          // Wax^T, lo

// ---------------------------------------------------------------------------
// f32x2 helpers (recurrence)
// ---------------------------------------------------------------------------
__device__ __forceinline__ uint64_t pack2(float lo, float hi)
{
    uint64_t r;
    asm("mov.b64 %0, {%1, %2};" : "=l"(r)
        : "r"(__float_as_uint(lo)), "r"(__float_as_uint(hi)));
    return r;
}
__device__ __forceinline__ uint64_t fma2(uint64_t a, uint64_t b, uint64_t c)
{
    uint64_t d;
    asm("fma.rn.f32x2 %0, %1, %2, %3;" : "=l"(d) : "l"(a), "l"(b), "l"(c));
    return d;
}
__device__ __forceinline__ void unpack2(uint64_t v, float& lo, float& hi)
{
    uint32_t l, h;
    asm("mov.b64 {%0, %1}, %2;" : "=r"(l), "=r"(h) : "l"(v));
    lo = __uint_as_float(l); hi = __uint_as_float(h);
}
__device__ __forceinline__ void lds_v2b64(uint32_t addr, uint64_t& p, uint64_t& q)
{
    asm volatile("ld.shared.v2.b64 {%0, %1}, [%2];"
                 : "=l"(p), "=l"(q) : "r"(addr));
}

// tanh = 1 - 2/(e^{2x}+1) via ex2/rcp approx (~1e-6 rel err, saturates).
__device__ __forceinline__ float ftanh(float x)
{
    float e;
    asm("ex2.approx.f32 %0, %1;" : "=f"(e) : "f"(x * 2.885390081777927f));
    float r;
    asm("rcp.approx.f32 %0, %1;" : "=f"(r) : "f"(e + 1.0f));
    return fmaf(-2.0f, r, 1.0f);
}

__device__ __forceinline__ void mbar_wait(uint32_t mbar, uint32_t parity)
{
    uint32_t done;
    asm volatile(
        "{\n\t.reg .pred p;\n\t"
        "mbarrier.try_wait.parity.acquire.cta.shared::cta.b64 p, [%1], %2;\n\t"
        "selp.b32 %0, 1, 0, p;\n\t}"
        : "=r"(done) : "r"(mbar), "r"(parity) : "memory");
    if (!done) {
        asm volatile(
            "{\n\t.reg .pred P1;\n\t"
            "W_%=:\n\t"
            "mbarrier.try_wait.parity.acquire.cta.shared::cta.b64 P1, [%0], %1, 0x989680;\n\t"
            "@P1 bra.uni D_%=;\n\t"
            "bra.uni W_%=;\n\t"
            "D_%=:\n\t}"
            :: "r"(mbar), "r"(parity) : "memory");
    }
}

// ---------------------------------------------------------------------------
// Convert kernels: transpose + bf16 hi/lo split (GEMM inputs only)
// ---------------------------------------------------------------------------
__global__ void __launch_bounds__(256)
convert_x_kernel(const float* __restrict__ X)
{
    __shared__ float tile[32][33];
    const int b  = blockIdx.z;
    const int i0 = blockIdx.x * 32;
    const int t0 = blockIdx.y * 32;
    const int lane = threadIdx.x & 31;
    const int r4   = threadIdx.x >> 5;
    const float* Xb = X + (size_t)b * I_DIM * T_DIM;
#pragma unroll
    for (int rr = 0; rr < 4; rr++) {
        int irow = r4 * 4 + rr;
        tile[irow][lane] = Xb[(size_t)(i0 + irow) * T_DIM + t0 + lane];
    }
    __syncthreads();
#pragma unroll
    for (int rr = 0; rr < 4; rr++) {
        int trow = r4 * 4 + rr;
        float v = tile[lane][trow];
        __nv_bfloat16 hi = __float2bfloat16(v);
        float lo = v - __bfloat162float(hi);
        g_Xt_hi[b][t0 + trow][i0 + lane] = hi;
        g_Xt_lo[b][t0 + trow][i0 + lane] = __float2bfloat16(lo);
    }
}

__global__ void __launch_bounds__(256)
convert_w_kernel(const float* __restrict__ W)
{
    __shared__ float tile[32][33];
    const int i0 = blockIdx.x * 32;
    const int h0 = blockIdx.y * 32;
    const int lane = threadIdx.x & 31;
    const int r4   = threadIdx.x >> 5;
#pragma unroll
    for (int rr = 0; rr < 4; rr++) {
        int irow = r4 * 4 + rr;
        tile[irow][lane] = W[(size_t)(i0 + irow) * H_DIM + h0 + lane];
    }
    __syncthreads();
#pragma unroll
    for (int rr = 0; rr < 4; rr++) {
        int hrow = r4 * 4 + rr;
        float v = tile[lane][hrow];
        __nv_bfloat16 hi = __float2bfloat16(v);
        float lo = v - __bfloat162float(hi);
        g_Wt_hi[h0 + hrow][i0 + lane] = hi;
        g_Wt_lo[h0 + hrow][i0 + lane] = __float2bfloat16(lo);
    }
}

// ---------------------------------------------------------------------------
// mma.sync / ldmatrix helpers
// ---------------------------------------------------------------------------
__device__ __forceinline__ void ldsm4(uint32_t addr, uint32_t* r)
{
    asm volatile("ldmatrix.sync.aligned.m8n8.x4.shared.b16 {%0,%1,%2,%3}, [%4];"
                 : "=r"(r[0]), "=r"(r[1]), "=r"(r[2]), "=r"(r[3]) : "r"(addr));
}
__device__ __forceinline__ void mma16816(float* d, const uint32_t* a,
                                         uint32_t b0, uint32_t b1)
{
    asm volatile(
        "mma.sync.aligned.m16n8k16.row.col.f32.bf16.bf16.f32 "
        "{%0,%1,%2,%3}, {%4,%5,%6,%7}, {%8,%9}, {%0,%1,%2,%3};"
        : "+f"(d[0]), "+f"(d[1]), "+f"(d[2]), "+f"(d[3])
        : "r"(a[0]), "r"(a[1]), "r"(a[2]), "r"(a[3]), "r"(b0), "r"(b1));
}

// ---------------------------------------------------------------------------
// Kernel 1: U = Xt @ Wax^T(+bias), mma.sync bf16 hi/lo (proven, 127us)
// ---------------------------------------------------------------------------
__global__ void __launch_bounds__(256, 1)
u_gemm_kernel(float* __restrict__ U,
              const float* __restrict__ bx, const float* __restrict__ ba)
{
    extern __shared__ char smem[];
    const uint32_t smem_u = (uint32_t)__cvta_generic_to_shared(smem);
    const int tid  = threadIdx.x;
    const int wid  = tid >> 5;
    const int lane = tid & 31;
    const int h0 = blockIdx.x * 128;
    const int t0 = blockIdx.y * 128;
    const int b  = blockIdx.z;

    float* bias_s = (float*)(smem + 131072);
    if (tid < 128) bias_s[tid] = bx[h0 + tid] + ba[h0 + tid];

    auto load_stage = [&](int s) {
        const uint32_t buf = smem_u + (uint32_t)(s & 1) * 65536u;
        const int i0 = s * 64;
#pragma unroll
        for (int j = 0; j < 4; j++) {
            int chunk = tid + j * 256;
            int row = chunk >> 3, kc = chunk & 7;
            uint32_t sw = (uint32_t)(row * 128 + kc * 16);
            sw = sw ^ ((sw >> 3) & 0x70);
            const __nv_bfloat16* ga = &g_Xt_hi[b][t0 + row][i0 + kc * 8];
            const __nv_bfloat16* gb = &g_Xt_lo[b][t0 + row][i0 + kc * 8];
            const __nv_bfloat16* gc = &g_Wt_hi[h0 + row][i0 + kc * 8];
            const __nv_bfloat16* gd = &g_Wt_lo[h0 + row][i0 + kc * 8];
            asm volatile("cp.async.cg.shared.global [%0], [%1], 16;"
                         :: "r"(buf + sw), "l"(ga) : "memory");
            asm volatile("cp.async.cg.shared.global [%0], [%1], 16;"
                         :: "r"(buf + 16384u + sw), "l"(gb) : "memory");
            asm volatile("cp.async.cg.shared.global [%0], [%1], 16;"
                         :: "r"(buf + 32768u + sw), "l"(gc) : "memory");
            asm volatile("cp.async.cg.shared.global [%0], [%1], 16;"
                         :: "r"(buf + 49152u + sw), "l"(gd) : "memory");
        }
        asm volatile("cp.async.commit_group;" ::: "memory");
    };

    const int m_off = (wid & 1) * 64;
    const int n_off = (wid >> 1) * 32;

    const uint32_t aRowB = (uint32_t)(m_off + (lane & 15)) * 128u;
    const uint32_t aK8   = (uint32_t)(lane >> 4) * 16u;
    const uint32_t xmA   = (uint32_t)(lane & 7) * 16u;
    const int      brow  = (lane & 7) + ((lane >> 1) & 8);
    const uint32_t bRowB = (uint32_t)(n_off + brow) * 128u;
    const uint32_t bK8   = (uint32_t)(lane & 8) * 2u;
    const uint32_t xmB   = (uint32_t)(lane & 7) * 16u;

    float acc[4][4][4];
#pragma unroll
    for (int i = 0; i < 4; i++)
#pragma unroll
        for (int j = 0; j < 4; j++)
#pragma unroll
            for (int k = 0; k < 4; k++) acc[i][j][k] = 0.0f;

    load_stage(0);
    for (int s = 0; s < 8; s++) {
        if (s < 7) {
            load_stage(s + 1);
            asm volatile("cp.async.wait_group 1;" ::: "memory");
        } else {
            asm volatile("cp.async.wait_group 0;" ::: "memory");
        }
        __syncthreads();

        const uint32_t buf = smem_u + (uint32_t)(s & 1) * 65536u;
#pragma unroll
        for (int k16 = 0; k16 < 4; k16++) {
            const uint32_t colA = ((uint32_t)(k16 * 32) + aK8) ^ xmA;
            const uint32_t colB = ((uint32_t)(k16 * 32) + bK8) ^ xmB;
            uint32_t Ah[4][4], Al[4][4], Bh[2][4], Bl[2][4];
#pragma unroll
            for (int fm = 0; fm < 4; fm++) {
                const uint32_t ad = buf + aRowB + (uint32_t)fm * 2048u + colA;
                ldsm4(ad, Ah[fm]);
                ldsm4(ad + 16384u, Al[fm]);
            }
#pragma unroll
            for (int fn2 = 0; fn2 < 2; fn2++) {
                const uint32_t bd = buf + 32768u + bRowB + (uint32_t)fn2 * 2048u + colB;
                ldsm4(bd, Bh[fn2]);
                ldsm4(bd + 16384u, Bl[fn2]);
            }
#pragma unroll
            for (int fm = 0; fm < 4; fm++) {
#pragma unroll
                for (int fn = 0; fn < 4; fn++) {
                    const int g = fn >> 1, o = (fn & 1) * 2;
                    mma16816(acc[fm][fn], Ah[fm], Bh[g][o], Bh[g][o + 1]);
                    mma16816(acc[fm][fn], Ah[fm], Bl[g][o], Bl[g][o + 1]);
                    mma16816(acc[fm][fn], Al[fm], Bh[g][o], Bh[g][o + 1]);
                }
            }
        }
        __syncthreads();
    }

    const int row_l = lane >> 2;
    const int col_l = (lane & 3) * 2;
#pragma unroll
    for (int fm = 0; fm < 4; fm++) {
#pragma unroll
        for (int fn = 0; fn < 4; fn++) {
            const int cl = n_off + fn * 8 + col_l;
            const float bi0 = bias_s[cl], bi1 = bias_s[cl + 1];
            const int r0 = t0 + m_off + fm * 16 + row_l;
            float* up0 = U + (size_t)r0 * (B_DIM * H_DIM) + (size_t)b * H_DIM + h0 + cl;
            float2 v0 = make_float2(acc[fm][fn][0] + bi0, acc[fm][fn][1] + bi1);
            *(float2*)up0 = v0;
            float* up1 = up0 + 8 * (B_DIM * H_DIM);
            float2 v1 = make_float2(acc[fm][fn][2] + bi0, acc[fm][fn][3] + bi1);
            *(float2*)up1 = v1;
        }
    }
}

// ---------------------------------------------------------------------------
// Kernel 2: cluster recurrence, 2-group pipelined FFMA2 edition (R14 fixed:
// barrier stride is g*128, NOT g*256 — 32 barriers live in bytes [0,256)).
// 16 clusters x 8 CTAs; cluster owns 4 batch rows = TWO independent 2-row
// recurrence chains (groups). 1024 phases alternate groups: while group g's
// DSMEM sends are in flight, group g^1 computes -> waits hit the fast path.
// SMEM: [0,256)B mbarriers bar[g][src][par] at g*128+src*16+par*8 |
//       ab[2 g][3 buf][8 rank][2 b][64 k] f32 | Red[2 g][8 ks][2 b][64 hh].
// ---------------------------------------------------------------------------
__global__ void __launch_bounds__(512, 1) __cluster_dims__(8, 1, 1)
recurrence_kernel(const float* __restrict__ Waa, float* __restrict__ A)
{
    extern __shared__ float sm[];
    float* ab  = sm + 64;            // 6144 floats
    float* Red = ab + 6144;          // 2048 floats

    const int tid = threadIdx.x;
    uint32_t rank;
    asm("mov.u32 %0, %%cluster_ctarank;" : "=r"(rank));
    const int cl = blockIdx.x >> 3;
    const int b0 = cl * 4;
    const int n0 = (int)rank * 64;
    const int ks = tid >> 6;          // strip 0..7 (2 warps each)
    const int hh = tid & 63;
    const int k0 = ks * 64;

    const uint32_t mbar0 = (uint32_t)__cvta_generic_to_shared(sm);
    const uint32_t ab_s  = (uint32_t)__cvta_generic_to_shared(ab);

    uint32_t peer_ab[8];
#pragma unroll
    for (int r = 0; r < 8; r++) {
        asm("mapa.shared::cluster.u32 %0, %1, %2;"
            : "=r"(peer_ab[r]) : "r"(ab_s), "r"(r));
    }

    // Waa strip in registers, f32x2 (k,k+1) pairs (identical to R9).
    uint64_t wd[32];
#pragma unroll
    for (int i = 0; i < 16; i++) {
        const float* wp = Waa + (size_t)(k0 + 4 * i) * H_DIM + n0 + hh;
        wd[2 * i]     = pack2(wp[0 * H_DIM], wp[1 * H_DIM]);
        wd[2 * i + 1] = pack2(wp[2 * H_DIM], wp[3 * H_DIM]);
    }

    if (tid < 32) {
        asm volatile("mbarrier.init.shared.b64 [%0], 1;"
                     :: "r"(mbar0 + tid * 8) : "memory");
    }
    for (int i = tid; i < 6144; i += 512) ab[i] = 0.0f;   // a_0 = 0 (both groups)
    __syncthreads();
    if (tid < 32) {                                        // arm both parities
        asm volatile("mbarrier.arrive.expect_tx.shared.b64 _, [%0], %1;"
                     :: "r"(mbar0 + tid * 8), "r"(512u) : "memory");
    }
    asm volatile("barrier.cluster.arrive.aligned;" ::: "memory");
    asm volatile("barrier.cluster.wait.aligned;" ::: "memory");

    const int eb = (tid >> 6) & 1;        // epilogue row within group (tid<128)
    const int eh = tid & 63;
    // byte offset of this thread's value inside a buffer: [rank][b][k]
    const uint32_t eoff = rank * 512u + (uint32_t)(eb * 64 + eh) * 4u;

    for (int p = 0; p < 2 * T_DIM; p++) {
        const int g = p & 1;
        const int t = p >> 1;
        const int cb = t % 3, nb = (t + 1) % 3;

        // Prefetch U (d_out holds U[t] at this element).
        float u = 0.0f;
        if (tid < 128)
            u = __ldcs(&A[(size_t)t * (B_DIM * H_DIM)
                          + (size_t)(b0 + 2 * g + eb) * H_DIM + n0 + eh]);

        if (t > 0) {
            const uint32_t obj = mbar0 +
                (uint32_t)(g * 128 + ks * 16 + ((t - 1) & 1) * 8);
            mbar_wait(obj, (uint32_t)(((t - 1) >> 1) & 1));
            if ((tid & 63) == 0) {            // re-arm for reuse at step t+1
                asm volatile("mbarrier.arrive.expect_tx.shared.b64 _, [%0], %1;"
                             :: "r"(obj), "r"(512u) : "memory");
            }
        }

        // Compute: group g, buffer cb, strip ks block [2 b][64 k].
        const uint32_t sbase = ab_s +
            (uint32_t)(g * 3072 + cb * 1024 + ks * 128) * 4u;
        uint64_t a0 = 0, a1 = 0;
#pragma unroll
        for (int i = 0; i < 16; i++) {
            uint64_t pq0, pq1;
            lds_v2b64(sbase + i * 16u, pq0, pq1);
            a0 = fma2(pq0, wd[2 * i], a0); a0 = fma2(pq1, wd[2 * i + 1], a0);
            lds_v2b64(sbase + 256u + i * 16u, pq0, pq1);
            a1 = fma2(pq0, wd[2 * i], a1); a1 = fma2(pq1, wd[2 * i + 1], a1);
        }
        float l0, h0, l1, h1;
        unpack2(a0, l0, h0);
        unpack2(a1, l1, h1);
        float* Rp = Red + g * 1024 + ks * 128 + hh;   // [g][ks][b][hh]
        Rp[0]  = l0 + h0;
        Rp[64] = l1 + h1;
        __syncthreads();

        if (tid < 128) {
            const float* Rr = Red + g * 1024 + eb * 64 + eh;
            float s = u;
#pragma unroll
            for (int w8 = 0; w8 < 8; w8++)
                s += Rr[w8 * 128];
            float val = ftanh(s);

            if (t < T_DIM - 1) {
                const uint32_t doff =
                    (uint32_t)(g * 3072 + nb * 1024) * 4u + eoff;
                const uint32_t boff =
                    (uint32_t)(g * 128 + rank * 16 + (t & 1) * 8);
#pragma unroll
                for (int r = 0; r < 8; r++) {
                    const uint32_t da = peer_ab[r] + doff;
                    const uint32_t ma = peer_ab[r] - 256u + boff;
                    asm volatile(
                        "st.async.shared::cluster.mbarrier::complete_tx::bytes.f32 "
                        "[%0], %1, [%2];"
                        :: "r"(da), "f"(val), "r"(ma) : "memory");
                }
            }
            __stcs(&A[(size_t)t * (B_DIM * H_DIM)
                      + (size_t)(b0 + 2 * g + eb) * H_DIM + n0 + eh], val);
        }
    }

    asm volatile("barrier.cluster.arrive.aligned;" ::: "memory");
    asm volatile("barrier.cluster.wait.aligned;" ::: "memory");
}

// ---------------------------------------------------------------------------
extern "C" void kernel_launch(void* const* d_in, const int* in_sizes, int n_in,
                              void* d_out, int out_size)
{
    const float* X   = (const float*)d_in[0];
    const float* Wax = (const float*)d_in[1];
    const float* Waa = (const float*)d_in[2];
    const float* bx  = (const float*)d_in[3];
    const float* ba  = (const float*)d_in[4];
    float* out = (float*)d_out;

    const int gemm_smem = 132 * 1024;
    cudaFuncSetAttribute(u_gemm_kernel,
                         cudaFuncAttributeMaxDynamicSharedMemorySize, gemm_smem);
    const int rec_smem = 140 * 1024;   // actual ~33KB; pin 1 CTA/SM
    cudaFuncSetAttribute(recurrence_kernel,
                         cudaFuncAttributeMaxDynamicSharedMemorySize, rec_smem);

    convert_x_kernel<<<dim3(16, 16, 64), 256>>>(X);
    convert_w_kernel<<<dim3(16, 16), 256>>>(Wax);
    u_gemm_kernel<<<dim3(4, 4, 64), 256, gemm_smem>>>(out, bx, ba);
    recurrence_kernel<<<128, 512, rec_smem>>>(Waa, out);
}